// round 10
// baseline (speedup 1.0000x reference)
#include <cuda_runtime.h>

// out[b, :] = table_bits[idx(b), :],  idx(b) = sum_k idx_bits[b,k] << (5-k)
// Table values are 0/1 pulses -> packed once into 64-bit masks (build kernel).
// Main kernel: 512B smem mask table + 256B smem nibble->float4 LUT (ALU-built).
// Hot loop per row: shift+and -> LDS.128(LUT) -> contiguous STG.128.

#define BATCH   262144
#define THREADS 256
#define ROWS_PER_WARP 16
#define GRID (BATCH / (ROWS_PER_WARP * (THREADS / 32)))   // 2048 blocks

// Mask for table row r: column c (0..63) lives at bit (63 - c).
__device__ unsigned long long g_masks[64];

__global__ void build_masks_kernel(const float* __restrict__ table)
{
    int w    = (blockIdx.x * blockDim.x + threadIdx.x) >> 5;   // 0..63 table row
    int lane = threadIdx.x & 31;
    float v0 = table[w * 64 + lane];        // cols 0..31
    float v1 = table[w * 64 + 32 + lane];   // cols 32..63
    unsigned hi = __brev(__ballot_sync(0xFFFFFFFFu, v0 > 0.5f)); // col c -> bit 31-c
    unsigned lo = __brev(__ballot_sync(0xFFFFFFFFu, v1 > 0.5f));
    if (lane == 0)
        g_masks[w] = ((unsigned long long)hi << 32) | (unsigned long long)lo;
}

__global__ __launch_bounds__(THREADS)
void spike_lookup_kernel(const int* __restrict__ bits,    // BATCH*6
                         float4*    __restrict__ out4)    // BATCH*16
{
    __shared__ unsigned long long sm[64];   // 512 B mask table
    __shared__ float4 lut[16];              // nibble -> {bit3,bit2,bit1,bit0} floats

    const int lane  = threadIdx.x & 31;
    const int gwarp = blockIdx.x * (THREADS / 32) + (threadIdx.x >> 5);

    // ---- Issue bits loads FIRST (latency hides under smem fill + barrier) ----
    const int* __restrict__ p = bits + gwarp * 96;   // 16 rows * 6 ints
    int v0 = p[lane];
    int v1 = p[lane + 32];
    int v2 = p[lane + 64];

    if (threadIdx.x < 64)
        sm[threadIdx.x] = g_masks[threadIdx.x];      // L1-hot LDG.64
    if (threadIdx.x < 16) {
        unsigned n = threadIdx.x;
        float4 e;
        e.x = (float)((n >> 3) & 1u);
        e.y = (float)((n >> 2) & 1u);
        e.z = (float)((n >> 1) & 1u);
        e.w = (float)( n       & 1u);
        lut[n] = e;
    }
    __syncthreads();

    unsigned b0 = __ballot_sync(0xFFFFFFFFu, v0 != 0);  // int m -> bit m
    unsigned b1 = __ballot_sync(0xFFFFFFFFu, v1 != 0);
    unsigned b2 = __ballot_sync(0xFFFFFFFFu, v2 != 0);

    unsigned long long u01 = (unsigned long long)b0 | ((unsigned long long)b1 << 32);
    unsigned long long u12 = (unsigned long long)b1 | ((unsigned long long)b2 << 32);

    const int j    = lane & 15;        // float4 column within the 64-float row
    const int half = lane >> 4;        // row parity within the pair
    const int s    = 60 - 4 * j;       // cols 4j..4j+3 -> nibble bits 3..0

    // All 8 indices up front: pure ALU.
    int idxv[8];
    #pragma unroll
    for (int i = 0; i < 8; i++) {
        int r  = 2 * i + half;                    // local row 0..15
        int sh = 6 * r;
        unsigned vb = (r < 10) ? (unsigned)(u01 >> sh)
                               : (unsigned)(u12 >> (sh - 32));
        idxv[i] = (int)(__brev(vb & 63u) >> 26);  // k=0 is MSB (weight 32)
    }

    // 8 broadcast mask reads (conflict-free LDS.64).
    unsigned long long m[8];
    #pragma unroll
    for (int i = 0; i < 8; i++)
        m[i] = sm[idxv[i]];

    // Hot loop: 2 ALU + LDS.128 + contiguous STG.128 per row.
    float4* __restrict__ dst = out4 + (long long)gwarp * 256 + lane;
    #pragma unroll
    for (int i = 0; i < 8; i++) {
        unsigned nib = (unsigned)(m[i] >> s) & 0xFu;
        dst[i * 32] = lut[nib];                   // 512B contiguous per warp
    }
}

extern "C" void kernel_launch(void* const* d_in, const int* in_sizes, int n_in,
                              void* d_out, int out_size)
{
    const float* table = (const float*)d_in[0];
    const int*   bits  = (const int*)d_in[1];
    float4*      out4  = (float4*)d_out;

    build_masks_kernel<<<2, 1024>>>(table);           // 64 warps, one per row
    spike_lookup_kernel<<<GRID, THREADS>>>(bits, out4);
}

// round 11
// speedup vs baseline: 1.1332x; 1.1332x over previous
#include <cuda_runtime.h>

// out[b, :] = table_bits[idx(b), :],  idx(b) = sum_k idx_bits[b,k] << (5-k)
// Table values are 0/1 pulses -> packed ONCE into 64-bit masks, stored
// PRE-REVERSED: g2[v] = mask of table row brev6(v), so the hot loop indexes
// with the raw ballot window (no brev). Hot loop = R7's winning schedule:
// 2 groups of {4x ALU index, 4x LDG.64 broadcast, 4x expand + STG.128}.

#define BATCH   262144
#define THREADS 256
#define ROWS_PER_WARP 16
#define GRID (BATCH / (ROWS_PER_WARP * (THREADS / 32)))   // 2048 blocks

// g2[v] = mask of table row rev6(v); column c (0..63) at bit (63 - c).
__device__ unsigned long long g2[64];

__global__ void build_masks_kernel(const float* __restrict__ table)
{
    int w    = (blockIdx.x * blockDim.x + threadIdx.x) >> 5;   // 0..63 table row
    int lane = threadIdx.x & 31;
    float v0 = table[w * 64 + lane];        // cols 0..31
    float v1 = table[w * 64 + 32 + lane];   // cols 32..63
    unsigned hi = __brev(__ballot_sync(0xFFFFFFFFu, v0 > 0.5f)); // col c -> bit 31-c
    unsigned lo = __brev(__ballot_sync(0xFFFFFFFFu, v1 > 0.5f));
    if (lane == 0) {
        int v = (int)(__brev((unsigned)w) >> 26);    // rev6(w)
        g2[v] = ((unsigned long long)hi << 32) | (unsigned long long)lo;
    }
}

__device__ __forceinline__ float bit_to_1f(unsigned nib, int k)
{
    // nibble bit (3-k) -> 0.0f / 1.0f  (1.0f = 0x3F800000)
    return __int_as_float(((int)(nib << (28 + k)) >> 31) & 0x3F800000);
}

__global__ __launch_bounds__(THREADS, 8)
void spike_lookup_kernel(const int* __restrict__ bits,    // BATCH*6
                         float4*    __restrict__ out4)    // BATCH*16
{
    const int lane  = threadIdx.x & 31;
    const int gwarp = blockIdx.x * (THREADS / 32) + (threadIdx.x >> 5);

    // 16 rows * 6 ints = 96 ints, fully coalesced (L2-resident in steady state).
    const int* __restrict__ p = bits + gwarp * 96;
    unsigned c0 = __ballot_sync(0xFFFFFFFFu, p[lane]      != 0); // int m -> bit m
    unsigned c1 = __ballot_sync(0xFFFFFFFFu, p[lane + 32] != 0);
    unsigned c2 = __ballot_sync(0xFFFFFFFFu, p[lane + 64] != 0);

    const int j    = lane & 15;        // float4 column within the 64-float row
    const int half = lane >> 4;        // row parity within the pair
    const int s    = 60 - 4 * j;       // cols 4j..4j+3 -> nibble bits 3..0
    const int hb   = 6 * half;         // bit offset delta for odd rows

    float4* __restrict__ dst = out4 + (long long)gwarp * 256 + lane;

    #pragma unroll
    for (int g = 0; g < 2; g++) {
        // ---- 4 window extractions (1 funnel shift each, raw index: table
        //      is pre-reversed so no brev) ----
        unsigned idxv[4];
        #pragma unroll
        for (int i = 0; i < 4; i++) {
            int r  = 2 * (g * 4 + i);          // even-row id; +half via hb
            int sh = 6 * r + hb;               // 0..90
            // select source pair by sh>>5 (mostly compile-time after unroll)
            unsigned lo, hi;
            if (sh + 6 <= 32)      { lo = c0; hi = c1; }
            else if (sh < 32)      { lo = c0; hi = c1; }
            else if (sh + 6 <= 64) { lo = c1; hi = c2; }
            else if (sh < 64)      { lo = c1; hi = c2; }
            else                   { lo = c2; hi = 0;  }
            idxv[i] = __funnelshift_r(lo, hi, sh) & 63u;
        }

        // ---- 4 broadcast mask loads (L1-hot, 1 line each) ----
        unsigned long long m[4];
        #pragma unroll
        for (int i = 0; i < 4; i++)
            m[i] = __ldg(&g2[idxv[i]]);

        // ---- 4 expands + contiguous STG.128 (512B per warp) ----
        #pragma unroll
        for (int i = 0; i < 4; i++) {
            unsigned nib = (unsigned)(m[i] >> s) & 0xFu;
            float4 v;
            v.x = bit_to_1f(nib, 0);
            v.y = bit_to_1f(nib, 1);
            v.z = bit_to_1f(nib, 2);
            v.w = bit_to_1f(nib, 3);
            dst[(g * 4 + i) * 32] = v;
        }
    }
}

extern "C" void kernel_launch(void* const* d_in, const int* in_sizes, int n_in,
                              void* d_out, int out_size)
{
    const float* table = (const float*)d_in[0];
    const int*   bits  = (const int*)d_in[1];
    float4*      out4  = (float4*)d_out;

    build_masks_kernel<<<2, 1024>>>(table);           // 64 warps, one per row
    spike_lookup_kernel<<<GRID, THREADS>>>(bits, out4);
}

// round 12
// speedup vs baseline: 1.1356x; 1.0021x over previous
#include <cuda_runtime.h>

// out[b, :] = table_bits[idx(b), :],  idx(b) = sum_k idx_bits[b,k] << (5-k)
// Table values are 0/1 pulses -> packed ONCE into 64-bit masks, stored
// PRE-REVERSED: g2[v] = mask of table row rev6(v), so the hot loop indexes
// with the raw ballot window. 8 rows/warp -> 32K warps for latency hiding.

#define BATCH   262144
#define THREADS 256
#define ROWS_PER_WARP 8
#define GRID (BATCH / (ROWS_PER_WARP * (THREADS / 32)))   // 4096 blocks

// g2[v] = mask of table row rev6(v); column c (0..63) at bit (63 - c).
__device__ unsigned long long g2[64];

__global__ void build_masks_kernel(const float* __restrict__ table)
{
    int w    = (blockIdx.x * blockDim.x + threadIdx.x) >> 5;   // 0..63 table row
    int lane = threadIdx.x & 31;
    float v0 = table[w * 64 + lane];        // cols 0..31
    float v1 = table[w * 64 + 32 + lane];   // cols 32..63
    unsigned hi = __brev(__ballot_sync(0xFFFFFFFFu, v0 > 0.5f)); // col c -> bit 31-c
    unsigned lo = __brev(__ballot_sync(0xFFFFFFFFu, v1 > 0.5f));
    if (lane == 0) {
        int v = (int)(__brev((unsigned)w) >> 26);    // rev6(w)
        g2[v] = ((unsigned long long)hi << 32) | (unsigned long long)lo;
    }
}

__device__ __forceinline__ float bit_to_1f(unsigned nib, int k)
{
    // nibble bit (3-k) -> 0.0f / 1.0f  (1.0f = 0x3F800000)
    return __int_as_float(((int)(nib << (28 + k)) >> 31) & 0x3F800000);
}

__global__ __launch_bounds__(THREADS, 8)
void spike_lookup_kernel(const int* __restrict__ bits,    // BATCH*6
                         float4*    __restrict__ out4)    // BATCH*16
{
    const int lane  = threadIdx.x & 31;
    const int gwarp = blockIdx.x * (THREADS / 32) + (threadIdx.x >> 5);

    // 8 rows * 6 ints = 48 ints; 1 full + 1 half-predicated coalesced LDG.
    const int* __restrict__ p = bits + gwarp * 48;
    int v0 = p[lane];
    int v1 = (lane < 16) ? p[lane + 32] : 0;

    unsigned b0 = __ballot_sync(0xFFFFFFFFu, v0 != 0);  // int m -> bit m
    unsigned b1 = __ballot_sync(0xFFFFFFFFu, v1 != 0);
    unsigned long long u = (unsigned long long)b0 | ((unsigned long long)b1 << 32);

    const int j    = lane & 15;        // float4 column within the 64-float row
    const int half = lane >> 4;        // row parity within the pair
    const int s    = 60 - 4 * j;       // cols 4j..4j+3 -> nibble bits 3..0
    const int hb   = 6 * half;         // bit offset delta for odd rows

    // ---- 4 window extractions (raw index: table is pre-reversed) ----
    unsigned idxv[4];
    #pragma unroll
    for (int i = 0; i < 4; i++) {
        int sh = 12 * i + hb;                     // row r = 2i+half at bits sh..sh+5
        idxv[i] = (unsigned)(u >> sh) & 63u;
    }

    // ---- 4 broadcast mask loads (L1-hot, <=2 lines per warp each) ----
    unsigned long long m[4];
    #pragma unroll
    for (int i = 0; i < 4; i++)
        m[i] = __ldg(&g2[idxv[i]]);

    // ---- 4 expands + contiguous STG.128 (512B per warp each) ----
    float4* __restrict__ dst = out4 + (long long)gwarp * 128 + lane;
    #pragma unroll
    for (int i = 0; i < 4; i++) {
        unsigned nib = (unsigned)(m[i] >> s) & 0xFu;
        float4 v;
        v.x = bit_to_1f(nib, 0);
        v.y = bit_to_1f(nib, 1);
        v.z = bit_to_1f(nib, 2);
        v.w = bit_to_1f(nib, 3);
        dst[i * 32] = v;
    }
}

extern "C" void kernel_launch(void* const* d_in, const int* in_sizes, int n_in,
                              void* d_out, int out_size)
{
    const float* table = (const float*)d_in[0];
    const int*   bits  = (const int*)d_in[1];
    float4*      out4  = (float4*)d_out;

    build_masks_kernel<<<2, 1024>>>(table);           // 64 warps, one per row
    spike_lookup_kernel<<<GRID, THREADS>>>(bits, out4);
}